// round 1
// baseline (speedup 1.0000x reference)
#include <cuda_runtime.h>
#include <math.h>

// Problem constants (fixed by the dataset)
#define B_TOK 16384
#define K_TOP 2
#define E_EXP 64
#define H_DIM 512
#define F_DIM 1024
#define N_ASG (B_TOK * K_TOP)   // 32768 assignments
#define CAP   (N_ASG / E_EXP)   // 512 per expert (balanced routing)

// Scratch (device globals — no runtime allocation allowed)
__device__ int   d_cnt[E_EXP];
__device__ int   d_slotmap[N_ASG];                       // [e*CAP + pos] = assignment index n
__device__ float d_hid[(size_t)E_EXP * CAP * F_DIM];     // 134 MB: silu(x @ W1)
__device__ float d_y[(size_t)N_ASG * H_DIM];             // 67 MB: per-assignment y (unweighted)

__global__ void zero_counts_kernel() {
    if (threadIdx.x < E_EXP) d_cnt[threadIdx.x] = 0;
}

__global__ void route_kernel(const int* __restrict__ expert_ids) {
    int n = blockIdx.x * blockDim.x + threadIdx.x;
    if (n < N_ASG) {
        int e = expert_ids[n];
        int p = atomicAdd(&d_cnt[e], 1);
        d_slotmap[e * CAP + p] = n;
    }
}

// ---------------------------------------------------------------------------
// GEMM1: per expert e, C[m][f] = silu( sum_h x[tok(m)][h] * W1[e][h][f] )
// M=CAP=512 (gathered rows), K=H=512, N=F=1024.
// Tiles: 128x128x16, 256 threads, 8x8 per thread.
// ---------------------------------------------------------------------------
__global__ __launch_bounds__(256)
void gemm1_kernel(const float* __restrict__ hidden, const float* __restrict__ W1) {
    const int e  = blockIdx.z;
    const int tm = blockIdx.y;   // 0..3
    const int tn = blockIdx.x;   // 0..7

    __shared__ float As[16][128];      // [k][m]
    __shared__ float Bs[16][128];      // [k][n]
    __shared__ int   rowTok[128];

    const int tid = threadIdx.x;

    if (tid < 128) {
        int n = d_slotmap[e * CAP + tm * 128 + tid];
        rowTok[tid] = n >> 1;          // token = n / K_TOP (K=2)
    }
    __syncthreads();

    const int tx = tid & 15;           // 0..15 -> N cols tx*8..tx*8+7
    const int ty = tid >> 4;           // 0..15 -> M rows ty*8..ty*8+7

    float acc[8][8];
#pragma unroll
    for (int i = 0; i < 8; i++)
#pragma unroll
        for (int j = 0; j < 8; j++) acc[i][j] = 0.0f;

    const float* Bbase = W1 + (size_t)e * H_DIM * F_DIM + tn * 128;

    // A-load mapping: 512 float4 per tile, 2 per thread
    const int a_row0 = tid >> 2;               // 0..63
    const int a_kc   = (tid & 3) * 4;          // 0,4,8,12
    // B-load mapping: 512 float4 per tile, 2 per thread
    const int b_kr0  = tid >> 5;               // 0..7
    const int b_nc   = (tid & 31) * 4;         // 0..124

    for (int k0 = 0; k0 < H_DIM; k0 += 16) {
        // load A tile (gathered rows), transposed into As[k][m]
#pragma unroll
        for (int r = 0; r < 2; r++) {
            int row = a_row0 + r * 64;
            const float* src = hidden + (size_t)rowTok[row] * H_DIM + k0 + a_kc;
            float4 v = *(const float4*)src;
            As[a_kc + 0][row] = v.x;
            As[a_kc + 1][row] = v.y;
            As[a_kc + 2][row] = v.z;
            As[a_kc + 3][row] = v.w;
        }
        // load B tile (contiguous along N)
#pragma unroll
        for (int r = 0; r < 2; r++) {
            int kr = b_kr0 + r * 8;
            const float* src = Bbase + (size_t)(k0 + kr) * F_DIM + b_nc;
            *(float4*)&Bs[kr][b_nc] = *(const float4*)src;
        }
        __syncthreads();

#pragma unroll
        for (int kk = 0; kk < 16; kk++) {
            float a[8], b[8];
#pragma unroll
            for (int i = 0; i < 8; i++) a[i] = As[kk][ty * 8 + i];
#pragma unroll
            for (int j = 0; j < 8; j++) b[j] = Bs[kk][tx * 8 + j];
#pragma unroll
            for (int i = 0; i < 8; i++)
#pragma unroll
                for (int j = 0; j < 8; j++) acc[i][j] = fmaf(a[i], b[j], acc[i][j]);
        }
        __syncthreads();
    }

    // epilogue: silu, write to d_hid
    float* dst = d_hid + ((size_t)e * CAP + tm * 128) * F_DIM + tn * 128;
#pragma unroll
    for (int i = 0; i < 8; i++) {
        float* drow = dst + (size_t)(ty * 8 + i) * F_DIM + tx * 8;
#pragma unroll
        for (int j4 = 0; j4 < 2; j4++) {
            float4 v;
            float s0 = acc[i][j4 * 4 + 0], s1 = acc[i][j4 * 4 + 1];
            float s2 = acc[i][j4 * 4 + 2], s3 = acc[i][j4 * 4 + 3];
            v.x = s0 / (1.0f + __expf(-s0));
            v.y = s1 / (1.0f + __expf(-s1));
            v.z = s2 / (1.0f + __expf(-s2));
            v.w = s3 / (1.0f + __expf(-s3));
            *(float4*)(drow + j4 * 4) = v;
        }
    }
}

// ---------------------------------------------------------------------------
// GEMM2: per expert e, y[m][h] = sum_f hid[e][m][f] * W2[e][f][h]
// M=CAP=512, K=F=1024, N=H=512. Scatter rows to d_y[assignment].
// ---------------------------------------------------------------------------
__global__ __launch_bounds__(256)
void gemm2_kernel(const float* __restrict__ W2) {
    const int e  = blockIdx.z;
    const int tm = blockIdx.y;   // 0..3
    const int tn = blockIdx.x;   // 0..3

    __shared__ float As[16][128];
    __shared__ float Bs[16][128];
    __shared__ int   rowAsg[128];

    const int tid = threadIdx.x;

    if (tid < 128) rowAsg[tid] = d_slotmap[e * CAP + tm * 128 + tid];
    __syncthreads();

    const int tx = tid & 15;
    const int ty = tid >> 4;

    float acc[8][8];
#pragma unroll
    for (int i = 0; i < 8; i++)
#pragma unroll
        for (int j = 0; j < 8; j++) acc[i][j] = 0.0f;

    const float* Abase = d_hid + ((size_t)e * CAP + tm * 128) * F_DIM;
    const float* Bbase = W2 + (size_t)e * F_DIM * H_DIM + tn * 128;

    const int a_row0 = tid >> 2;
    const int a_kc   = (tid & 3) * 4;
    const int b_kr0  = tid >> 5;
    const int b_nc   = (tid & 31) * 4;

    for (int k0 = 0; k0 < F_DIM; k0 += 16) {
#pragma unroll
        for (int r = 0; r < 2; r++) {
            int row = a_row0 + r * 64;
            const float* src = Abase + (size_t)row * F_DIM + k0 + a_kc;
            float4 v = *(const float4*)src;
            As[a_kc + 0][row] = v.x;
            As[a_kc + 1][row] = v.y;
            As[a_kc + 2][row] = v.z;
            As[a_kc + 3][row] = v.w;
        }
#pragma unroll
        for (int r = 0; r < 2; r++) {
            int kr = b_kr0 + r * 8;
            const float* src = Bbase + (size_t)(k0 + kr) * H_DIM + b_nc;
            *(float4*)&Bs[kr][b_nc] = *(const float4*)src;
        }
        __syncthreads();

#pragma unroll
        for (int kk = 0; kk < 16; kk++) {
            float a[8], b[8];
#pragma unroll
            for (int i = 0; i < 8; i++) a[i] = As[kk][ty * 8 + i];
#pragma unroll
            for (int j = 0; j < 8; j++) b[j] = Bs[kk][tx * 8 + j];
#pragma unroll
            for (int i = 0; i < 8; i++)
#pragma unroll
                for (int j = 0; j < 8; j++) acc[i][j] = fmaf(a[i], b[j], acc[i][j]);
        }
        __syncthreads();
    }

    // scatter rows into per-assignment buffer (deterministic: one writer per row)
#pragma unroll
    for (int i = 0; i < 8; i++) {
        int n = rowAsg[ty * 8 + i];
        float* drow = d_y + (size_t)n * H_DIM + tn * 128 + tx * 8;
#pragma unroll
        for (int j4 = 0; j4 < 2; j4++) {
            float4 v;
            v.x = acc[i][j4 * 4 + 0];
            v.y = acc[i][j4 * 4 + 1];
            v.z = acc[i][j4 * 4 + 2];
            v.w = acc[i][j4 * 4 + 3];
            *(float4*)(drow + j4 * 4) = v;
        }
    }
}

// ---------------------------------------------------------------------------
// Combine: out[t] = w[t,0]*y[2t] + w[t,1]*y[2t+1]  (deterministic, no atomics)
// ---------------------------------------------------------------------------
__global__ void combine_kernel(const float* __restrict__ expert_weights,
                               float* __restrict__ out) {
    const int HV = H_DIM / 4;   // 128 float4 per row
    long idx = (long)blockIdx.x * blockDim.x + threadIdx.x;
    long total = (long)B_TOK * HV;
    if (idx >= total) return;
    int t = (int)(idx / HV);
    int c = (int)(idx % HV);
    float w0 = expert_weights[2 * t];
    float w1 = expert_weights[2 * t + 1];
    const float4* y0 = (const float4*)(d_y + (size_t)(2 * t) * H_DIM) + c;
    const float4* y1 = (const float4*)(d_y + (size_t)(2 * t + 1) * H_DIM) + c;
    float4 a = *y0, b = *y1;
    float4 r;
    r.x = w0 * a.x + w1 * b.x;
    r.y = w0 * a.y + w1 * b.y;
    r.z = w0 * a.z + w1 * b.z;
    r.w = w0 * a.w + w1 * b.w;
    ((float4*)out)[idx] = r;
}

extern "C" void kernel_launch(void* const* d_in, const int* in_sizes, int n_in,
                              void* d_out, int out_size) {
    const float* hidden = (const float*)d_in[0];   // [B, H] f32
    const float* ew     = (const float*)d_in[1];   // [B, K] f32
    const int*   ids    = (const int*)d_in[2];     // [B, K] i32
    const float* W1     = (const float*)d_in[3];   // [E, H, F] f32
    const float* W2     = (const float*)d_in[4];   // [E, F, H] f32
    float* out = (float*)d_out;                    // [B, H] f32

    zero_counts_kernel<<<1, 64>>>();
    route_kernel<<<(N_ASG + 255) / 256, 256>>>(ids);

    dim3 g1(F_DIM / 128, CAP / 128, E_EXP);   // (8, 4, 64)
    gemm1_kernel<<<g1, 256>>>(hidden, W1);

    dim3 g2(H_DIM / 128, CAP / 128, E_EXP);   // (4, 4, 64)
    gemm2_kernel<<<g2, 256>>>(W2);

    long total = (long)B_TOK * (H_DIM / 4);
    combine_kernel<<<(int)((total + 255) / 256), 256>>>(ew, out);
}

// round 3
// speedup vs baseline: 3.1835x; 3.1835x over previous
#include <cuda_runtime.h>
#include <cstdint>

// ---------------------------------------------------------------------------
// Problem constants
// ---------------------------------------------------------------------------
#define B_TOK 16384
#define K_TOP 2
#define E_EXP 64
#define H_DIM 512
#define F_DIM 1024
#define N_ASG 32768            // B*K assignments
#define CAP   512              // per-expert (balanced routing)

// GEMM tiling: CTA 128x128, K-stage 32, 3-stage cp.async pipeline
#define STAGES 3
#define A_SM_STRIDE 36          // floats per A smem row (pad: conflict-free frags)
#define B_SM_STRIDE 136         // floats per B smem row
#define A_SM_FLOATS (128 * A_SM_STRIDE)            // 4608
#define B_SM_FLOATS (32 * B_SM_STRIDE)             // 4352
#define STAGE_FLOATS (A_SM_FLOATS + B_SM_FLOATS)   // 8960
#define STAGE_BYTES  (STAGE_FLOATS * 4)            // 35840
#define A_SM_BYTES   (A_SM_FLOATS * 4)             // 18432
#define DYN_SMEM     (STAGES * STAGE_BYTES)        // 107520

// ---------------------------------------------------------------------------
// Scratch (device globals)
// ---------------------------------------------------------------------------
__device__ int   d_cnt[E_EXP];
__device__ int   d_slot[N_ASG];   // [e*CAP + p] = assignment n
__device__ int   d_pos[N_ASG];    // [n] = e*CAP + p
__device__ float d_hid[(size_t)N_ASG * F_DIM];   // 134 MB: silu(x@W1), grouped rows
__device__ float d_yg [(size_t)N_ASG * H_DIM];   //  67 MB: grouped outputs

// ---------------------------------------------------------------------------
// PTX helpers (all base-sm_100-legal: sm_80/sm_90 vintage)
// ---------------------------------------------------------------------------
__device__ __forceinline__ uint32_t smem_u32(const void* p) {
    uint32_t a;
    asm("{ .reg .u64 t; cvta.to.shared.u64 t, %1; cvt.u32.u64 %0, t; }" : "=r"(a) : "l"(p));
    return a;
}
__device__ __forceinline__ uint32_t tf32b(float x) {
    uint32_t r;
    asm("cvt.rna.tf32.f32 %0, %1;" : "=r"(r) : "f"(x));
    return r;
}
__device__ __forceinline__ void cp16(uint32_t dst, const void* src) {
    asm volatile("cp.async.cg.shared.global [%0], [%1], 16;" :: "r"(dst), "l"(src));
}
#define CP_COMMIT() asm volatile("cp.async.commit_group;" ::: "memory")
#define CP_WAIT2()  asm volatile("cp.async.wait_group 2;" ::: "memory")

__device__ __forceinline__ void mma_tf32(float* c, const uint32_t* a,
                                         uint32_t b0, uint32_t b1) {
    asm volatile(
        "mma.sync.aligned.m16n8k8.row.col.f32.tf32.tf32.f32 "
        "{%0,%1,%2,%3}, {%4,%5,%6,%7}, {%8,%9}, {%0,%1,%2,%3};"
        : "+f"(c[0]), "+f"(c[1]), "+f"(c[2]), "+f"(c[3])
        : "r"(a[0]), "r"(a[1]), "r"(a[2]), "r"(a[3]), "r"(b0), "r"(b1));
}

__device__ __forceinline__ float silu(float x) { return x / (1.0f + __expf(-x)); }

// ---------------------------------------------------------------------------
// Routing
// ---------------------------------------------------------------------------
__global__ void zero_counts_kernel() {
    if (threadIdx.x < E_EXP) d_cnt[threadIdx.x] = 0;
}
__global__ void route_kernel(const int* __restrict__ expert_ids) {
    int n = blockIdx.x * blockDim.x + threadIdx.x;
    if (n < N_ASG) {
        int e = expert_ids[n];
        int p = atomicAdd(&d_cnt[e], 1);
        d_slot[e * CAP + p] = n;
        d_pos[n] = e * CAP + p;
    }
}

// ---------------------------------------------------------------------------
// tf32 mma.sync GEMM, CTA tile 128x128.
//   C[m][n] = sum_k A[m][k] * W[k][n], per expert e (blockIdx.z).
// GATHER: A rows indexed via d_slot (token gather). SILU: epilogue activation.
// KT: number of 32-wide K stages. NG: global N (row stride of W and Out).
// AS: global row stride of A.
// ---------------------------------------------------------------------------
template<int KT, int NG, int AS, bool GATHER, bool SILU>
__global__ __launch_bounds__(256)
void mma_gemm_kernel(const float* __restrict__ Aglob,
                     const float* __restrict__ Wglob,
                     float* __restrict__ Out) {
    extern __shared__ __align__(16) float sm[];
    __shared__ int toks[128];

    const int e  = blockIdx.z;
    const int mt = blockIdx.y;
    const int nt = blockIdx.x;
    const int tid = threadIdx.x;

    if (GATHER) {
        if (tid < 128) {
            int n = d_slot[(e * 4 + mt) * 128 + tid];
            toks[tid] = n >> 1;                 // token = n / K_TOP (K=2)
        }
        __syncthreads();
    }

    const float* Abase = GATHER ? Aglob
                                : (Aglob + (size_t)((e * 4 + mt) * 128) * AS);
    const float* Bbase = Wglob + (size_t)e * (KT * 32) * NG + nt * 128;
    const uint32_t smb = smem_u32(sm);

    // stage issue: 4 A-chunks + 4 B-chunks of 16B per thread
    auto issue = [&](int kt) {
        const int slot = kt % STAGES;
        const uint32_t sA = smb + slot * STAGE_BYTES;
        const uint32_t sB = sA + A_SM_BYTES;
#pragma unroll
        for (int j = 0; j < 4; j++) {
            int idx = tid + j * 256;            // 0..1023
            int row = idx >> 3, c = idx & 7;
            const float* src = GATHER
                ? Aglob + (size_t)toks[row] * AS + kt * 32 + c * 4
                : Abase + (size_t)row * AS + kt * 32 + c * 4;
            cp16(sA + row * (A_SM_STRIDE * 4) + c * 16, src);
        }
#pragma unroll
        for (int j = 0; j < 4; j++) {
            int idx = tid + j * 256;
            int kr = idx >> 5, c = idx & 31;
            cp16(sB + kr * (B_SM_STRIDE * 4) + c * 16,
                 Bbase + (size_t)(kt * 32 + kr) * NG + c * 4);
        }
    };

    const int wid  = tid >> 5, lane = tid & 31;
    const int g    = lane >> 2, tg = lane & 3;
    const int wm   = wid & 1;                    // 2 warps along M (64 each)
    const int wn   = wid >> 1;                   // 4 warps along N (32 each)

    float c[4][4][4];
#pragma unroll
    for (int i = 0; i < 4; i++)
#pragma unroll
        for (int j = 0; j < 4; j++)
#pragma unroll
            for (int k = 0; k < 4; k++) c[i][j][k] = 0.0f;

    // prologue: stages 0,1
    issue(0); CP_COMMIT();
    issue(1); CP_COMMIT();

#pragma unroll 1
    for (int kt = 0; kt < KT; kt++) {
        if (kt + 2 < KT) issue(kt + 2);
        CP_COMMIT();                             // empty group near tail: keeps count
        CP_WAIT2();                              // stage kt complete (this thread)
        __syncthreads();                         // ...and all threads

        const float* As = sm + (kt % STAGES) * STAGE_FLOATS;
        const float* Bs = As + A_SM_FLOATS;

#pragma unroll
        for (int k8 = 0; k8 < 4; k8++) {
            const int kk = k8 * 8;
            uint32_t a[4][4];
#pragma unroll
            for (int ma = 0; ma < 4; ma++) {
                int m0 = wm * 64 + ma * 16 + g;
                a[ma][0] = tf32b(As[m0 * A_SM_STRIDE + kk + tg]);
                a[ma][1] = tf32b(As[(m0 + 8) * A_SM_STRIDE + kk + tg]);
                a[ma][2] = tf32b(As[m0 * A_SM_STRIDE + kk + tg + 4]);
                a[ma][3] = tf32b(As[(m0 + 8) * A_SM_STRIDE + kk + tg + 4]);
            }
#pragma unroll
            for (int na = 0; na < 4; na++) {
                int nn = wn * 32 + na * 8 + g;
                uint32_t b0 = tf32b(Bs[(kk + tg) * B_SM_STRIDE + nn]);
                uint32_t b1 = tf32b(Bs[(kk + tg + 4) * B_SM_STRIDE + nn]);
#pragma unroll
                for (int ma = 0; ma < 4; ma++)
                    mma_tf32(c[ma][na], a[ma], b0, b1);
            }
        }
        __syncthreads();                         // before overwriting slot kt%3
    }

    // epilogue
#pragma unroll
    for (int ma = 0; ma < 4; ma++) {
        size_t gr = (size_t)(e * 4 + mt) * 128 + wm * 64 + ma * 16 + g;
#pragma unroll
        for (int na = 0; na < 4; na++) {
            int col = nt * 128 + wn * 32 + na * 8 + 2 * tg;
            float2 v0, v1;
            if (SILU) {
                v0.x = silu(c[ma][na][0]); v0.y = silu(c[ma][na][1]);
                v1.x = silu(c[ma][na][2]); v1.y = silu(c[ma][na][3]);
            } else {
                v0.x = c[ma][na][0]; v0.y = c[ma][na][1];
                v1.x = c[ma][na][2]; v1.y = c[ma][na][3];
            }
            *(float2*)(Out + gr * NG + col)        = v0;
            *(float2*)(Out + (gr + 8) * NG + col)  = v1;
        }
    }
}

// ---------------------------------------------------------------------------
// Combine: out[t] = w0*yg[pos(2t)] + w1*yg[pos(2t+1)]
// ---------------------------------------------------------------------------
__global__ __launch_bounds__(256)
void combine_kernel(const float* __restrict__ expert_weights, float* __restrict__ out) {
    int idx = blockIdx.x * 256 + threadIdx.x;    // one float4 of out; 2M total
    int t = idx >> 7, cc = idx & 127;
    float w0 = expert_weights[2 * t];
    float w1 = expert_weights[2 * t + 1];
    int g0 = d_pos[2 * t], g1 = d_pos[2 * t + 1];
    float4 a = ((const float4*)(d_yg + (size_t)g0 * H_DIM))[cc];
    float4 b = ((const float4*)(d_yg + (size_t)g1 * H_DIM))[cc];
    float4 rr;
    rr.x = w0 * a.x + w1 * b.x;
    rr.y = w0 * a.y + w1 * b.y;
    rr.z = w0 * a.z + w1 * b.z;
    rr.w = w0 * a.w + w1 * b.w;
    ((float4*)out)[idx] = rr;
}

// ---------------------------------------------------------------------------
// Launch
// ---------------------------------------------------------------------------
extern "C" void kernel_launch(void* const* d_in, const int* in_sizes, int n_in,
                              void* d_out, int out_size) {
    const float* hidden = (const float*)d_in[0];   // [B, H]
    const float* ew     = (const float*)d_in[1];   // [B, K]
    const int*   ids    = (const int*)d_in[2];     // [B, K]
    const float* W1     = (const float*)d_in[3];   // [E, H, F]
    const float* W2     = (const float*)d_in[4];   // [E, F, H]
    float* out = (float*)d_out;

    // gemm1: M=512/expert (gathered tokens), K=H=512, N=F=1024, silu
    auto* k1 = mma_gemm_kernel<16, F_DIM, H_DIM, true, true>;
    // gemm2: M=512/expert (grouped hid), K=F=1024, N=H=512
    auto* k2 = mma_gemm_kernel<32, H_DIM, F_DIM, false, false>;
    cudaFuncSetAttribute(k1, cudaFuncAttributeMaxDynamicSharedMemorySize, DYN_SMEM);
    cudaFuncSetAttribute(k2, cudaFuncAttributeMaxDynamicSharedMemorySize, DYN_SMEM);

    zero_counts_kernel<<<1, 64>>>();
    route_kernel<<<(N_ASG + 255) / 256, 256>>>(ids);

    float* hid_ptr = nullptr; float* yg_ptr = nullptr;
    cudaGetSymbolAddress((void**)&hid_ptr, d_hid);
    cudaGetSymbolAddress((void**)&yg_ptr, d_yg);

    dim3 g1(F_DIM / 128, CAP / 128, E_EXP);   // (8, 4, 64)
    k1<<<g1, 256, DYN_SMEM>>>(hidden, W1, hid_ptr);

    dim3 g2(H_DIM / 128, CAP / 128, E_EXP);   // (4, 4, 64)
    k2<<<g2, 256, DYN_SMEM>>>(hid_ptr, W2, yg_ptr);

    combine_kernel<<<(B_TOK * (H_DIM / 4)) / 256, 256>>>(ew, out);
}

// round 4
// speedup vs baseline: 4.7862x; 1.5034x over previous
#include <cuda_runtime.h>
#include <cuda_fp16.h>
#include <cstdint>

// ---------------------------------------------------------------------------
// Problem constants
// ---------------------------------------------------------------------------
#define B_TOK 16384
#define K_TOP 2
#define E_EXP 64
#define H_DIM 512
#define F_DIM 1024
#define N_ASG 32768            // B*K assignments
#define CAP   512              // per-expert (balanced routing)

// GEMM tiling: CTA 128x128, K-stage 64 (fp16), 3-stage cp.async pipeline
#define STAGES 3
#define TILE_ROW_BYTES 128                       // 64 halves, XOR-swizzled chunks
#define A_SM_BYTES (128 * TILE_ROW_BYTES)        // 16384
#define STAGE_BYTES (2 * A_SM_BYTES)             // 32768 (A + B)
#define DYN_SMEM (STAGES * STAGE_BYTES)          // 98304 -> 2 CTAs/SM

// ---------------------------------------------------------------------------
// Scratch (device globals)
// ---------------------------------------------------------------------------
__device__ int    d_cnt[E_EXP];
__device__ int    d_slot[N_ASG];    // [e*CAP + p] = assignment n
__device__ int    d_pos[N_ASG];     // [n] = e*CAP + p
__device__ __half d_xh [(size_t)B_TOK * H_DIM];          //  17 MB hidden fp16
__device__ __half d_w1h[(size_t)E_EXP * F_DIM * H_DIM];  //  67 MB W1^T  [e][f][h]
__device__ __half d_w2h[(size_t)E_EXP * H_DIM * F_DIM];  //  67 MB W2^T  [e][h][f]
__device__ __half d_hidh[(size_t)N_ASG * F_DIM];         //  67 MB silu(x@W1) fp16
__device__ float  d_yg [(size_t)N_ASG * H_DIM];          //  67 MB grouped outputs f32

// ---------------------------------------------------------------------------
// PTX helpers (sm_80-vintage, base-sm_100 legal)
// ---------------------------------------------------------------------------
__device__ __forceinline__ uint32_t smem_u32(const void* p) {
    uint32_t a;
    asm("{ .reg .u64 t; cvta.to.shared.u64 t, %1; cvt.u32.u64 %0, t; }" : "=r"(a) : "l"(p));
    return a;
}
__device__ __forceinline__ void cp16(uint32_t dst, const void* src) {
    asm volatile("cp.async.cg.shared.global [%0], [%1], 16;" :: "r"(dst), "l"(src));
}
#define CP_COMMIT() asm volatile("cp.async.commit_group;" ::: "memory")
#define CP_WAIT2()  asm volatile("cp.async.wait_group 2;" ::: "memory")

__device__ __forceinline__ void mma_f16(float* c, const uint32_t* a, const uint32_t* b) {
    asm volatile(
        "mma.sync.aligned.m16n8k16.row.col.f32.f16.f16.f32 "
        "{%0,%1,%2,%3}, {%4,%5,%6,%7}, {%8,%9}, {%0,%1,%2,%3};"
        : "+f"(c[0]), "+f"(c[1]), "+f"(c[2]), "+f"(c[3])
        : "r"(a[0]), "r"(a[1]), "r"(a[2]), "r"(a[3]), "r"(b[0]), "r"(b[1]));
}
__device__ __forceinline__ float silu(float x) { return x / (1.0f + __expf(-x)); }

// ---------------------------------------------------------------------------
// Routing
// ---------------------------------------------------------------------------
__global__ void zero_counts_kernel() {
    if (threadIdx.x < E_EXP) d_cnt[threadIdx.x] = 0;
}
__global__ void route_kernel(const int* __restrict__ expert_ids) {
    int n = blockIdx.x * blockDim.x + threadIdx.x;
    if (n < N_ASG) {
        int e = expert_ids[n];
        int p = atomicAdd(&d_cnt[e], 1);
        d_slot[e * CAP + p] = n;
        d_pos[n] = e * CAP + p;
    }
}

// ---------------------------------------------------------------------------
// hidden f32 -> fp16 (RN), 8 elements per thread
// ---------------------------------------------------------------------------
__global__ __launch_bounds__(256)
void conv_x_kernel(const float* __restrict__ src) {
    size_t i = ((size_t)blockIdx.x * 256 + threadIdx.x) * 8;
    float4 v0 = *(const float4*)(src + i);
    float4 v1 = *(const float4*)(src + i + 4);
    __half2 h[4];
    h[0] = __floats2half2_rn(v0.x, v0.y);
    h[1] = __floats2half2_rn(v0.z, v0.w);
    h[2] = __floats2half2_rn(v1.x, v1.y);
    h[3] = __floats2half2_rn(v1.z, v1.w);
    *(uint4*)(d_xh + i) = *(uint4*)h;
}

// ---------------------------------------------------------------------------
// Transpose-convert: src f32 [e][KD][ND] -> dst fp16 [e][ND][KD]
// ---------------------------------------------------------------------------
template<int KD, int ND>
__global__ __launch_bounds__(256)
void transconv_kernel(const float* __restrict__ src, __half* __restrict__ dst) {
    __shared__ float tile[32][33];
    const int e = blockIdx.z, kb = blockIdx.y, nb = blockIdx.x;
    const int t = threadIdx.x;
    const float* s = src + (size_t)e * KD * ND + (size_t)kb * 32 * ND + nb * 32;
#pragma unroll
    for (int j = 0; j < 4; j++) {
        int i = t + j * 256;
        int k_l = i >> 5, n_l = i & 31;
        tile[k_l][n_l] = s[(size_t)k_l * ND + n_l];
    }
    __syncthreads();
    {
        int n_l = t >> 3, kq = t & 7;
        __half2 h[2];
        h[0] = __floats2half2_rn(tile[kq * 4 + 0][n_l], tile[kq * 4 + 1][n_l]);
        h[1] = __floats2half2_rn(tile[kq * 4 + 2][n_l], tile[kq * 4 + 3][n_l]);
        __half* d = dst + ((size_t)e * ND + nb * 32 + n_l) * KD + kb * 32 + kq * 4;
        *(uint2*)d = *(uint2*)h;
    }
}

// ---------------------------------------------------------------------------
// fp16 mma GEMM, CTA tile 128x128, K-stage 64.
//   C[m][n] = sum_k A[m][k] * B[n][k]   (B stored n-major = W^T), expert e.
// KG: K dim (A & B row length). NG: output row stride / B n-rows per expert.
// GATHER: A rows via d_slot. SILU: silu + fp16 out, else f32 out.
// ---------------------------------------------------------------------------
template<int KG, int NG, bool GATHER, bool SILU>
__global__ __launch_bounds__(256, 2)
void hgemm_kernel(const __half* __restrict__ Aglob,
                  const __half* __restrict__ Bglob,
                  void* __restrict__ OutP) {
    extern __shared__ __align__(16) __half sm[];
    __shared__ int toks[128];

    const int e  = blockIdx.z;
    const int mt = blockIdx.y;
    const int nt = blockIdx.x;
    const int tid = threadIdx.x;
    const int KT = KG / 64;

    if (GATHER) {
        if (tid < 128) {
            int n = d_slot[(e * 4 + mt) * 128 + tid];
            toks[tid] = n >> 1;                  // token = n / K_TOP
        }
        __syncthreads();
    }

    const __half* Abase = GATHER ? Aglob
                                 : (Aglob + (size_t)((e * 4 + mt) * 128) * KG);
    const __half* Bbase = Bglob + ((size_t)e * NG + nt * 128) * KG;
    const uint32_t smb = smem_u32(sm);

    // stage issue: 4 A-chunks + 4 B-chunks of 16B per thread, XOR-swizzled
    auto issue = [&](int kt) {
        const int slot = kt % STAGES;
        const uint32_t sA = smb + slot * STAGE_BYTES;
        const uint32_t sB = sA + A_SM_BYTES;
#pragma unroll
        for (int j = 0; j < 4; j++) {
            int idx = tid + j * 256;             // 0..1023
            int row = idx >> 3, c = idx & 7;
            const __half* src = GATHER
                ? Aglob + (size_t)toks[row] * KG + kt * 64 + c * 8
                : Abase + (size_t)row * KG + kt * 64 + c * 8;
            cp16(sA + row * TILE_ROW_BYTES + ((c ^ (row & 7)) * 16), src);
        }
#pragma unroll
        for (int j = 0; j < 4; j++) {
            int idx = tid + j * 256;
            int row = idx >> 3, c = idx & 7;
            cp16(sB + row * TILE_ROW_BYTES + ((c ^ (row & 7)) * 16),
                 Bbase + (size_t)row * KG + kt * 64 + c * 8);
        }
    };

    const int wid  = tid >> 5, lane = tid & 31;
    const int g    = lane >> 2, tg = lane & 3;
    const int wm   = wid & 1;                    // 2 warps along M (64 each)
    const int wn   = wid >> 1;                   // 4 warps along N (32 each)

    float c[4][4][4];
#pragma unroll
    for (int i = 0; i < 4; i++)
#pragma unroll
        for (int j = 0; j < 4; j++)
#pragma unroll
            for (int k = 0; k < 4; k++) c[i][j][k] = 0.0f;

    issue(0); CP_COMMIT();
    issue(1); CP_COMMIT();

    // fragment offset in halves: row r, 16B-chunk ch (swizzled), half-lane 2*tg
    auto foff = [&](int r, int ch) { return r * 64 + ((ch ^ (r & 7)) * 8) + tg * 2; };

#pragma unroll 1
    for (int kt = 0; kt < KT; kt++) {
        if (kt + 2 < KT) issue(kt + 2);
        CP_COMMIT();
        CP_WAIT2();
        __syncthreads();

        const __half* As = sm + (size_t)(kt % STAGES) * (STAGE_BYTES / 2);
        const __half* Bs = As + A_SM_BYTES / 2;

#pragma unroll
        for (int k16 = 0; k16 < 4; k16++) {
            uint32_t a[4][4], b[4][2];
#pragma unroll
            for (int ma = 0; ma < 4; ma++) {
                int m0 = wm * 64 + ma * 16 + g;
                a[ma][0] = *(const uint32_t*)(As + foff(m0,     2 * k16));
                a[ma][1] = *(const uint32_t*)(As + foff(m0 + 8, 2 * k16));
                a[ma][2] = *(const uint32_t*)(As + foff(m0,     2 * k16 + 1));
                a[ma][3] = *(const uint32_t*)(As + foff(m0 + 8, 2 * k16 + 1));
            }
#pragma unroll
            for (int na = 0; na < 4; na++) {
                int nn = wn * 32 + na * 8 + g;
                b[na][0] = *(const uint32_t*)(Bs + foff(nn, 2 * k16));
                b[na][1] = *(const uint32_t*)(Bs + foff(nn, 2 * k16 + 1));
            }
#pragma unroll
            for (int ma = 0; ma < 4; ma++)
#pragma unroll
                for (int na = 0; na < 4; na++)
                    mma_f16(c[ma][na], a[ma], b[na]);
        }
        __syncthreads();
    }

    // epilogue
#pragma unroll
    for (int ma = 0; ma < 4; ma++) {
        size_t gr = (size_t)(e * 4 + mt) * 128 + wm * 64 + ma * 16 + g;
#pragma unroll
        for (int na = 0; na < 4; na++) {
            int col = nt * 128 + wn * 32 + na * 8 + 2 * tg;
            if (SILU) {
                __half* Out = (__half*)OutP;
                __half2 v0 = __floats2half2_rn(silu(c[ma][na][0]), silu(c[ma][na][1]));
                __half2 v1 = __floats2half2_rn(silu(c[ma][na][2]), silu(c[ma][na][3]));
                *(__half2*)(Out + gr * NG + col)       = v0;
                *(__half2*)(Out + (gr + 8) * NG + col) = v1;
            } else {
                float* Out = (float*)OutP;
                float2 v0 = {c[ma][na][0], c[ma][na][1]};
                float2 v1 = {c[ma][na][2], c[ma][na][3]};
                *(float2*)(Out + gr * NG + col)        = v0;
                *(float2*)(Out + (gr + 8) * NG + col)  = v1;
            }
        }
    }
}

// ---------------------------------------------------------------------------
// Combine: out[t] = w0*yg[pos(2t)] + w1*yg[pos(2t+1)]
// ---------------------------------------------------------------------------
__global__ __launch_bounds__(256)
void combine_kernel(const float* __restrict__ expert_weights, float* __restrict__ out) {
    int idx = blockIdx.x * 256 + threadIdx.x;
    int t = idx >> 7, cc = idx & 127;
    float w0 = expert_weights[2 * t];
    float w1 = expert_weights[2 * t + 1];
    int g0 = d_pos[2 * t], g1 = d_pos[2 * t + 1];
    float4 a = ((const float4*)(d_yg + (size_t)g0 * H_DIM))[cc];
    float4 b = ((const float4*)(d_yg + (size_t)g1 * H_DIM))[cc];
    float4 rr;
    rr.x = w0 * a.x + w1 * b.x;
    rr.y = w0 * a.y + w1 * b.y;
    rr.z = w0 * a.z + w1 * b.z;
    rr.w = w0 * a.w + w1 * b.w;
    ((float4*)out)[idx] = rr;
}

// ---------------------------------------------------------------------------
// Launch
// ---------------------------------------------------------------------------
extern "C" void kernel_launch(void* const* d_in, const int* in_sizes, int n_in,
                              void* d_out, int out_size) {
    const float* hidden = (const float*)d_in[0];   // [B, H]
    const float* ew     = (const float*)d_in[1];   // [B, K]
    const int*   ids    = (const int*)d_in[2];     // [B, K]
    const float* W1     = (const float*)d_in[3];   // [E, H, F]
    const float* W2     = (const float*)d_in[4];   // [E, F, H]
    float* out = (float*)d_out;

    // gemm1: K=H=512, N=F=1024, gathered A, silu, fp16 out
    auto* k1 = hgemm_kernel<H_DIM, F_DIM, true, true>;
    // gemm2: K=F=1024, N=H=512, f32 out
    auto* k2 = hgemm_kernel<F_DIM, H_DIM, false, false>;
    cudaFuncSetAttribute(k1, cudaFuncAttributeMaxDynamicSharedMemorySize, DYN_SMEM);
    cudaFuncSetAttribute(k2, cudaFuncAttributeMaxDynamicSharedMemorySize, DYN_SMEM);

    __half *xh, *w1h, *w2h, *hidh; float* yg;
    cudaGetSymbolAddress((void**)&xh,  d_xh);
    cudaGetSymbolAddress((void**)&w1h, d_w1h);
    cudaGetSymbolAddress((void**)&w2h, d_w2h);
    cudaGetSymbolAddress((void**)&hidh, d_hidh);
    cudaGetSymbolAddress((void**)&yg,  d_yg);

    zero_counts_kernel<<<1, 64>>>();
    route_kernel<<<(N_ASG + 255) / 256, 256>>>(ids);

    conv_x_kernel<<<(B_TOK * H_DIM) / (256 * 8), 256>>>(hidden);
    dim3 gt1(F_DIM / 32, H_DIM / 32, E_EXP);   // W1 [e][512][1024] -> [e][1024][512]
    transconv_kernel<H_DIM, F_DIM><<<gt1, 256>>>(W1, w1h);
    dim3 gt2(H_DIM / 32, F_DIM / 32, E_EXP);   // W2 [e][1024][512] -> [e][512][1024]
    transconv_kernel<F_DIM, H_DIM><<<gt2, 256>>>(W2, w2h);

    dim3 g1(F_DIM / 128, CAP / 128, E_EXP);    // (8, 4, 64)
    k1<<<g1, 256, DYN_SMEM>>>(xh, w1h, hidh);

    dim3 g2(H_DIM / 128, CAP / 128, E_EXP);    // (4, 4, 64)
    k2<<<g2, 256, DYN_SMEM>>>(hidh, w2h, yg);

    combine_kernel<<<(B_TOK * (H_DIM / 4)) / 256, 256>>>(ew, out);
}

// round 5
// speedup vs baseline: 5.0886x; 1.0632x over previous
#include <cuda_runtime.h>
#include <cuda_fp16.h>
#include <cstdint>

// ---------------------------------------------------------------------------
// Problem constants
// ---------------------------------------------------------------------------
#define B_TOK 16384
#define K_TOP 2
#define E_EXP 64
#define H_DIM 512
#define F_DIM 1024
#define N_ASG 32768            // B*K assignments
#define CAP   512              // per-expert (balanced routing)

// GEMM tiling: CTA 128x128, K-stage 64 (fp16), 3-stage cp.async pipeline
#define STAGES 3
#define TILE_ROW_BYTES 128                       // 64 halves, XOR-swizzled chunks
#define A_SM_BYTES (128 * TILE_ROW_BYTES)        // 16384
#define STAGE_BYTES (2 * A_SM_BYTES)             // 32768 (A + B)
#define DYN_SMEM (STAGES * STAGE_BYTES)          // 98304 -> 2 CTAs/SM

// ---------------------------------------------------------------------------
// Scratch (device globals)
// ---------------------------------------------------------------------------
__device__ int    d_cnt[E_EXP];
__device__ int    d_slot[N_ASG];    // [e*CAP + p] = assignment n
__device__ int    d_pos[N_ASG];     // [n] = e*CAP + p
__device__ __half d_xh [(size_t)B_TOK * H_DIM];          //  17 MB hidden fp16
__device__ __half d_w1h[(size_t)E_EXP * F_DIM * H_DIM];  //  67 MB W1^T  [e][f][h]
__device__ __half d_w2h[(size_t)E_EXP * H_DIM * F_DIM];  //  67 MB W2^T  [e][h][f]
__device__ __half d_hidh[(size_t)N_ASG * F_DIM];         //  67 MB silu(x@W1) fp16
__device__ float  d_yg [(size_t)N_ASG * H_DIM];          //  67 MB grouped outputs f32

// ---------------------------------------------------------------------------
// PTX helpers (sm_80-vintage, base-sm_100 legal)
// ---------------------------------------------------------------------------
__device__ __forceinline__ uint32_t smem_u32(const void* p) {
    uint32_t a;
    asm("{ .reg .u64 t; cvta.to.shared.u64 t, %1; cvt.u32.u64 %0, t; }" : "=r"(a) : "l"(p));
    return a;
}
__device__ __forceinline__ void cp16(uint32_t dst, const void* src) {
    asm volatile("cp.async.cg.shared.global [%0], [%1], 16;" :: "r"(dst), "l"(src));
}
#define CP_COMMIT() asm volatile("cp.async.commit_group;" ::: "memory")
#define CP_WAIT2()  asm volatile("cp.async.wait_group 2;" ::: "memory")

__device__ __forceinline__ void ldsm_x4(uint32_t* r, uint32_t addr) {
    asm volatile("ldmatrix.sync.aligned.m8n8.x4.shared.b16 {%0,%1,%2,%3}, [%4];"
                 : "=r"(r[0]), "=r"(r[1]), "=r"(r[2]), "=r"(r[3]) : "r"(addr));
}
__device__ __forceinline__ void mma_f16(float* c, const uint32_t* a, const uint32_t* b) {
    asm volatile(
        "mma.sync.aligned.m16n8k16.row.col.f32.f16.f16.f32 "
        "{%0,%1,%2,%3}, {%4,%5,%6,%7}, {%8,%9}, {%0,%1,%2,%3};"
        : "+f"(c[0]), "+f"(c[1]), "+f"(c[2]), "+f"(c[3])
        : "r"(a[0]), "r"(a[1]), "r"(a[2]), "r"(a[3]), "r"(b[0]), "r"(b[1]));
}
__device__ __forceinline__ float silu(float x) { return x / (1.0f + __expf(-x)); }

// ---------------------------------------------------------------------------
// Routing
// ---------------------------------------------------------------------------
__global__ void zero_counts_kernel() {
    if (threadIdx.x < E_EXP) d_cnt[threadIdx.x] = 0;
}
__global__ void route_kernel(const int* __restrict__ expert_ids) {
    int n = blockIdx.x * blockDim.x + threadIdx.x;
    if (n < N_ASG) {
        int e = expert_ids[n];
        int p = atomicAdd(&d_cnt[e], 1);
        d_slot[e * CAP + p] = n;
        d_pos[n] = e * CAP + p;
    }
}

// ---------------------------------------------------------------------------
// hidden f32 -> fp16 (RN), 8 elements per thread
// ---------------------------------------------------------------------------
__global__ __launch_bounds__(256)
void conv_x_kernel(const float* __restrict__ src) {
    size_t i = ((size_t)blockIdx.x * 256 + threadIdx.x) * 8;
    float4 v0 = *(const float4*)(src + i);
    float4 v1 = *(const float4*)(src + i + 4);
    __half2 h[4];
    h[0] = __floats2half2_rn(v0.x, v0.y);
    h[1] = __floats2half2_rn(v0.z, v0.w);
    h[2] = __floats2half2_rn(v1.x, v1.y);
    h[3] = __floats2half2_rn(v1.z, v1.w);
    *(uint4*)(d_xh + i) = *(uint4*)h;
}

// ---------------------------------------------------------------------------
// Transpose-convert: src f32 [e][KD][ND] -> dst fp16 [e][ND][KD]
// ---------------------------------------------------------------------------
template<int KD, int ND>
__global__ __launch_bounds__(256)
void transconv_kernel(const float* __restrict__ src, __half* __restrict__ dst) {
    __shared__ float tile[32][33];
    const int e = blockIdx.z, kb = blockIdx.y, nb = blockIdx.x;
    const int t = threadIdx.x;
    const float* s = src + (size_t)e * KD * ND + (size_t)kb * 32 * ND + nb * 32;
#pragma unroll
    for (int j = 0; j < 4; j++) {
        int i = t + j * 256;
        int k_l = i >> 5, n_l = i & 31;
        tile[k_l][n_l] = s[(size_t)k_l * ND + n_l];
    }
    __syncthreads();
    {
        int n_l = t >> 3, kq = t & 7;
        __half2 h[2];
        h[0] = __floats2half2_rn(tile[kq * 4 + 0][n_l], tile[kq * 4 + 1][n_l]);
        h[1] = __floats2half2_rn(tile[kq * 4 + 2][n_l], tile[kq * 4 + 3][n_l]);
        __half* d = dst + ((size_t)e * ND + nb * 32 + n_l) * KD + kb * 32 + kq * 4;
        *(uint2*)d = *(uint2*)h;
    }
}

// ---------------------------------------------------------------------------
// fp16 mma GEMM, CTA tile 128x128, K-stage 64, ldmatrix fragment loads.
//   C[m][n] = sum_k A[m][k] * B[n][k]   (B stored n-major = W^T), expert e.
// ---------------------------------------------------------------------------
template<int KG, int NG, bool GATHER, bool SILU>
__global__ __launch_bounds__(256, 2)
void hgemm_kernel(const __half* __restrict__ Aglob,
                  const __half* __restrict__ Bglob,
                  void* __restrict__ OutP) {
    extern __shared__ __align__(16) __half sm[];
    __shared__ int toks[128];

    const int e  = blockIdx.z;
    const int mt = blockIdx.y;
    const int nt = blockIdx.x;
    const int tid = threadIdx.x;
    const int KT = KG / 64;

    if (GATHER) {
        if (tid < 128) {
            int n = d_slot[(e * 4 + mt) * 128 + tid];
            toks[tid] = n >> 1;                  // token = n / K_TOP
        }
        __syncthreads();
    }

    const __half* Abase = GATHER ? Aglob
                                 : (Aglob + (size_t)((e * 4 + mt) * 128) * KG);
    const __half* Bbase = Bglob + ((size_t)e * NG + nt * 128) * KG;
    const uint32_t smb = smem_u32(sm);

    // stage issue: 4 A-chunks + 4 B-chunks of 16B per thread, XOR-swizzled
    auto issue = [&](int kt) {
        const int slot = kt % STAGES;
        const uint32_t sA = smb + slot * STAGE_BYTES;
        const uint32_t sB = sA + A_SM_BYTES;
#pragma unroll
        for (int j = 0; j < 4; j++) {
            int idx = tid + j * 256;             // 0..1023
            int row = idx >> 3, c = idx & 7;
            const __half* src = GATHER
                ? Aglob + (size_t)toks[row] * KG + kt * 64 + c * 8
                : Abase + (size_t)row * KG + kt * 64 + c * 8;
            cp16(sA + row * TILE_ROW_BYTES + ((c ^ (row & 7)) * 16), src);
        }
#pragma unroll
        for (int j = 0; j < 4; j++) {
            int idx = tid + j * 256;
            int row = idx >> 3, c = idx & 7;
            cp16(sB + row * TILE_ROW_BYTES + ((c ^ (row & 7)) * 16),
                 Bbase + (size_t)row * KG + kt * 64 + c * 8);
        }
    };

    const int wid  = tid >> 5, lane = tid & 31;
    const int g    = lane >> 2, tg = lane & 3;
    const int wm   = wid & 1;                    // 2 warps along M (64 each)
    const int wn   = wid >> 1;                   // 4 warps along N (32 each)

    // ldmatrix lane decomposition: tile index lt (0..3), row-in-tile lr (0..7)
    const int lt = lane >> 3, lr = lane & 7;

    // A x4 tiles: t0=(m-low,k-low) t1=(m-high,k-low) t2=(m-low,k-high) t3=(m-high,k-high)
    // lane address: row = mbase + (lt&1)*8 + lr, chunk = 2*k16 + (lt>>1)
    int a_row[4], a_xor[4];
#pragma unroll
    for (int ma = 0; ma < 4; ma++) {
        a_row[ma] = wm * 64 + ma * 16 + (lt & 1) * 8 + lr;
        a_xor[ma] = a_row[ma] & 7;
    }
    const int a_choff = lt >> 1;
    // B x4 tiles: t0=(n-low,k-low) t1=(n-low,k-high) t2=(n-high,k-low) t3=(n-high,k-high)
    // lane address: row = nbase + (lt>>1)*8 + lr, chunk = 2*k16 + (lt&1)
    int b_row[2], b_xor[2];
#pragma unroll
    for (int nb = 0; nb < 2; nb++) {
        b_row[nb] = wn * 32 + nb * 16 + (lt >> 1) * 8 + lr;
        b_xor[nb] = b_row[nb] & 7;
    }
    const int b_choff = lt & 1;

    float c[4][4][4];
#pragma unroll
    for (int i = 0; i < 4; i++)
#pragma unroll
        for (int j = 0; j < 4; j++)
#pragma unroll
            for (int k = 0; k < 4; k++) c[i][j][k] = 0.0f;

    issue(0); CP_COMMIT();
    issue(1); CP_COMMIT();

#pragma unroll 1
    for (int kt = 0; kt < KT; kt++) {
        if (kt + 2 < KT) issue(kt + 2);
        CP_COMMIT();
        CP_WAIT2();
        __syncthreads();

        const uint32_t sA = smb + (kt % STAGES) * STAGE_BYTES;
        const uint32_t sB = sA + A_SM_BYTES;

#pragma unroll
        for (int k16 = 0; k16 < 4; k16++) {
            uint32_t a[4][4], b[2][4];
#pragma unroll
            for (int ma = 0; ma < 4; ma++) {
                uint32_t addr = sA + a_row[ma] * TILE_ROW_BYTES
                              + (((2 * k16 + a_choff) ^ a_xor[ma]) << 4);
                ldsm_x4(a[ma], addr);
            }
#pragma unroll
            for (int nb = 0; nb < 2; nb++) {
                uint32_t addr = sB + b_row[nb] * TILE_ROW_BYTES
                              + (((2 * k16 + b_choff) ^ b_xor[nb]) << 4);
                ldsm_x4(b[nb], addr);
            }
#pragma unroll
            for (int ma = 0; ma < 4; ma++)
#pragma unroll
                for (int nb = 0; nb < 2; nb++) {
                    mma_f16(c[ma][2 * nb + 0], a[ma], &b[nb][0]);
                    mma_f16(c[ma][2 * nb + 1], a[ma], &b[nb][2]);
                }
        }
        __syncthreads();
    }

    // epilogue
#pragma unroll
    for (int ma = 0; ma < 4; ma++) {
        size_t gr = (size_t)(e * 4 + mt) * 128 + wm * 64 + ma * 16 + g;
#pragma unroll
        for (int na = 0; na < 4; na++) {
            int col = nt * 128 + wn * 32 + na * 8 + 2 * tg;
            if (SILU) {
                __half* Out = (__half*)OutP;
                __half2 v0 = __floats2half2_rn(silu(c[ma][na][0]), silu(c[ma][na][1]));
                __half2 v1 = __floats2half2_rn(silu(c[ma][na][2]), silu(c[ma][na][3]));
                *(__half2*)(Out + gr * NG + col)       = v0;
                *(__half2*)(Out + (gr + 8) * NG + col) = v1;
            } else {
                float* Out = (float*)OutP;
                float2 v0 = {c[ma][na][0], c[ma][na][1]};
                float2 v1 = {c[ma][na][2], c[ma][na][3]};
                *(float2*)(Out + gr * NG + col)        = v0;
                *(float2*)(Out + (gr + 8) * NG + col)  = v1;
            }
        }
    }
}

// ---------------------------------------------------------------------------
// Combine: out[t] = w0*yg[pos(2t)] + w1*yg[pos(2t+1)]
// ---------------------------------------------------------------------------
__global__ __launch_bounds__(256)
void combine_kernel(const float* __restrict__ expert_weights, float* __restrict__ out) {
    int idx = blockIdx.x * 256 + threadIdx.x;
    int t = idx >> 7, cc = idx & 127;
    float w0 = expert_weights[2 * t];
    float w1 = expert_weights[2 * t + 1];
    int g0 = d_pos[2 * t], g1 = d_pos[2 * t + 1];
    float4 a = ((const float4*)(d_yg + (size_t)g0 * H_DIM))[cc];
    float4 b = ((const float4*)(d_yg + (size_t)g1 * H_DIM))[cc];
    float4 rr;
    rr.x = w0 * a.x + w1 * b.x;
    rr.y = w0 * a.y + w1 * b.y;
    rr.z = w0 * a.z + w1 * b.z;
    rr.w = w0 * a.w + w1 * b.w;
    ((float4*)out)[idx] = rr;
}

// ---------------------------------------------------------------------------
// Launch
// ---------------------------------------------------------------------------
extern "C" void kernel_launch(void* const* d_in, const int* in_sizes, int n_in,
                              void* d_out, int out_size) {
    const float* hidden = (const float*)d_in[0];   // [B, H]
    const float* ew     = (const float*)d_in[1];   // [B, K]
    const int*   ids    = (const int*)d_in[2];     // [B, K]
    const float* W1     = (const float*)d_in[3];   // [E, H, F]
    const float* W2     = (const float*)d_in[4];   // [E, F, H]
    float* out = (float*)d_out;

    auto* k1 = hgemm_kernel<H_DIM, F_DIM, true, true>;
    auto* k2 = hgemm_kernel<F_DIM, H_DIM, false, false>;
    cudaFuncSetAttribute(k1, cudaFuncAttributeMaxDynamicSharedMemorySize, DYN_SMEM);
    cudaFuncSetAttribute(k2, cudaFuncAttributeMaxDynamicSharedMemorySize, DYN_SMEM);

    __half *xh, *w1h, *w2h, *hidh; float* yg;
    cudaGetSymbolAddress((void**)&xh,  d_xh);
    cudaGetSymbolAddress((void**)&w1h, d_w1h);
    cudaGetSymbolAddress((void**)&w2h, d_w2h);
    cudaGetSymbolAddress((void**)&hidh, d_hidh);
    cudaGetSymbolAddress((void**)&yg,  d_yg);

    zero_counts_kernel<<<1, 64>>>();
    route_kernel<<<(N_ASG + 255) / 256, 256>>>(ids);

    conv_x_kernel<<<(B_TOK * H_DIM) / (256 * 8), 256>>>(hidden);
    dim3 gt1(F_DIM / 32, H_DIM / 32, E_EXP);   // W1 [e][512][1024] -> [e][1024][512]
    transconv_kernel<H_DIM, F_DIM><<<gt1, 256>>>(W1, w1h);
    dim3 gt2(H_DIM / 32, F_DIM / 32, E_EXP);   // W2 [e][1024][512] -> [e][512][1024]
    transconv_kernel<F_DIM, H_DIM><<<gt2, 256>>>(W2, w2h);

    dim3 g1(F_DIM / 128, CAP / 128, E_EXP);    // (8, 4, 64)
    k1<<<g1, 256, DYN_SMEM>>>(xh, w1h, hidh);

    dim3 g2(H_DIM / 128, CAP / 128, E_EXP);    // (4, 4, 64)
    k2<<<g2, 256, DYN_SMEM>>>(hidh, w2h, yg);

    combine_kernel<<<(B_TOK * (H_DIM / 4)) / 256, 256>>>(ew, out);
}